// round 15
// baseline (speedup 1.0000x reference)
#include <cuda_runtime.h>
#include <math.h>

#define L_STEPS 24
#define NN 16384
#define LN (24*16384)          // 393216
#define HD 128
#define HP 136                 // padded node-major row pitch (floats)
#define DIN 136
#define KPAD 272               // padded K (17 chunks of 16)
#define GATES 512
#define SSTR 140

// ---------------- device scratch ----------------
__device__ __align__(128) float g_x[(size_t)DIN * LN];      // [k][LN] feature-major
__device__ __align__(128) float g_W[(size_t)KPAD * GATES];  // [k][col], col = d*4+gate
__device__ __align__(128) float g_cbias[GATES];
__device__ __align__(128) float g_stats[128];
__device__ __align__(128) float g_ss[64], g_st[64];
__device__ __align__(128) float g_h[(size_t)NN * HP];       // [n][136], cols 128..135 zero
__device__ __align__(128) float g_c[(size_t)NN * HD];       // [n][128]
__device__ __align__(128) float g_gh[(size_t)NN * HP];      // [n][136], cols 128..135 zero
__device__ __align__(128) float g_gc[(size_t)NN * HD];      // [n][128]

__device__ __forceinline__ float sigf(float x) { return 1.0f / (1.0f + expf(-x)); }
__device__ __forceinline__ unsigned pk(float lo, float hi) {
    unsigned r; asm("cvt.rn.bf16x2.f32 %0, %1, %2;" : "=r"(r) : "f"(hi), "f"(lo)); return r;
}

// ---------------- zero init: h, c, gh (incl pads), stats ----------------
__global__ void zero_kernel() {
    size_t i = (size_t)blockIdx.x * blockDim.x + threadIdx.x;
    size_t hp = (size_t)NN * HP, hd = (size_t)NN * HD;
    if (i < hp)                 g_h[i] = 0.0f;
    else if (i < hp + hd)       g_c[i - hp] = 0.0f;
    else if (i < 2 * hp + hd)   g_gh[i - hp - hd] = 0.0f;
    if (i < 128) g_stats[i] = 0.0f;
}

// ---------------- build lstm_in columns ----------------
__global__ __launch_bounds__(256) void build_x_kernel(
    const float* __restrict__ op, const float* __restrict__ attr,
    const float* __restrict__ filt, const float* __restrict__ outp,
    const float* __restrict__ Wf, const float* __restrict__ bf,
    const float* __restrict__ Wo, const float* __restrict__ bo)
{
    __shared__ __align__(16) float sWfT[74 * 32];
    __shared__ __align__(16) float sWoT[32 * 32];
    __shared__ float sbf[32], sbo[32];
    int tid = threadIdx.x;
    for (int i = tid; i < 74 * 32; i += 256) { int j = i / 74, k = i % 74; sWfT[k * 32 + j] = Wf[i]; }
    for (int i = tid; i < 32 * 32; i += 256) { int j = i / 32, k = i % 32; sWoT[k * 32 + j] = Wo[i]; }
    if (tid < 32) { sbf[tid] = bf[tid]; sbo[tid] = bo[tid]; }
    __syncthreads();

    size_t r = (size_t)blockIdx.x * 256 + tid;

    const float* opr = op + r * 16;
    #pragma unroll
    for (int k = 0; k < 16; k++) g_x[(size_t)k * LN + r] = opr[k];
    const float* atr = attr + r * 56;
    #pragma unroll 8
    for (int k = 0; k < 56; k++) g_x[(size_t)(16 + k) * LN + r] = atr[k];

    float acc[32];
    #pragma unroll
    for (int j = 0; j < 32; j++) acc[j] = sbf[j];
    const float* frow = filt + r * 74;
    for (int k = 0; k < 74; k++) {
        float fv = __ldg(&frow[k]);
        const float4* wrow = (const float4*)&sWfT[k * 32];
        #pragma unroll
        for (int j4 = 0; j4 < 8; j4++) {
            float4 w = wrow[j4];
            acc[j4*4+0] += fv * w.x; acc[j4*4+1] += fv * w.y;
            acc[j4*4+2] += fv * w.z; acc[j4*4+3] += fv * w.w;
        }
    }
    #pragma unroll
    for (int j = 0; j < 32; j++) {
        float v = acc[j]; v = v > 0.0f ? v : 0.01f * v;
        g_x[(size_t)(72 + j) * LN + r] = v;
    }
    #pragma unroll
    for (int j = 0; j < 32; j++) acc[j] = sbo[j];
    const float* orow = outp + r * 32;
    for (int k = 0; k < 32; k++) {
        float ov = __ldg(&orow[k]);
        const float4* wrow = (const float4*)&sWoT[k * 32];
        #pragma unroll
        for (int j4 = 0; j4 < 8; j4++) {
            float4 w = wrow[j4];
            acc[j4*4+0] += ov * w.x; acc[j4*4+1] += ov * w.y;
            acc[j4*4+2] += ov * w.z; acc[j4*4+3] += ov * w.w;
        }
    }
    #pragma unroll
    for (int j = 0; j < 32; j++) {
        float v = acc[j]; v = v > 0.0f ? v : 0.01f * v;
        g_x[(size_t)(104 + j) * LN + r] = v;
    }
}

// ---------------- BN stats over columns 72..135 ----------------
__global__ void stats_kernel() {
    int f = blockIdx.x;
    size_t col = (size_t)(72 + f) * LN;
    float s = 0.0f, q = 0.0f;
    for (size_t i = (size_t)blockIdx.y * blockDim.x + threadIdx.x; i < LN;
         i += (size_t)gridDim.y * blockDim.x) {
        float v = g_x[col + i];
        s += v; q += v * v;
    }
    for (int o = 16; o > 0; o >>= 1) {
        s += __shfl_down_sync(0xffffffffu, s, o);
        q += __shfl_down_sync(0xffffffffu, q, o);
    }
    __shared__ float shs[8], shq[8];
    int lane = threadIdx.x & 31, w = threadIdx.x >> 5;
    if (lane == 0) { shs[w] = s; shq[w] = q; }
    __syncthreads();
    if (threadIdx.x == 0) {
        float ts = 0.0f, tq = 0.0f;
        for (int i = 0; i < 8; i++) { ts += shs[i]; tq += shq[i]; }
        atomicAdd(&g_stats[f], ts);
        atomicAdd(&g_stats[64 + f], tq);
    }
}

// ---------------- BN fold ----------------
__global__ void fold_kernel(
    const float* __restrict__ g1, const float* __restrict__ beta1,
    const float* __restrict__ g2, const float* __restrict__ beta2)
{
    int tid = threadIdx.x;   // 64
    float mean = g_stats[tid] * (1.0f / (float)LN);
    float var  = g_stats[64 + tid] * (1.0f / (float)LN) - mean * mean;
    float gg = tid < 32 ? g1[tid] : g2[tid - 32];
    float bb = tid < 32 ? beta1[tid] : beta2[tid - 32];
    float sc = gg * rsqrtf(var + 1e-5f);
    g_ss[tid] = sc;
    g_st[tid] = bb - mean * sc;
}

// ---------------- combined bias ----------------
__global__ void cbias_kernel(
    const float* __restrict__ Wih,
    const float* __restrict__ bih, const float* __restrict__ bhh)
{
    int col = threadIdx.x;              // 512; col = d*4 + gate
    int gate = col & 3, d = col >> 2;
    int c = gate * 128 + d;
    const float* wr = Wih + (size_t)c * DIN;
    float cb = bih[c] + bhh[c];
    #pragma unroll
    for (int j = 0; j < 32; j++) cb += g_st[j] * wr[72 + j];
    #pragma unroll
    for (int j = 0; j < 32; j++) cb += g_st[32 + j] * wr[104 + j];
    g_cbias[col] = cb;
}

// ---------------- weight matrix build ----------------
__global__ void weight_kernel(const float* __restrict__ Wih, const float* __restrict__ Whh) {
    int k = blockIdx.x;                 // 0..271
    int col = threadIdx.x;              // 512
    int gate = col & 3, d = col >> 2;
    int c = gate * 128 + d;
    float w;
    if (k < 72)        w = Wih[(size_t)c * DIN + k];
    else if (k < 104)  w = Wih[(size_t)c * DIN + k] * g_ss[k - 72];
    else if (k < 136)  w = Wih[(size_t)c * DIN + k] * g_ss[32 + (k - 104)];
    else if (k < 264)  w = Whh[(size_t)c * HD + (k - 136)];
    else               w = 0.0f;
    g_W[(size_t)k * GATES + col] = w;
}

// ---------------- per-step neighbor gather (node-major, coalesced) ----------------
// 8 nodes per 256-thread block; 32 lanes per node read full rows as float4.
__global__ __launch_bounds__(256) void gather_kernel(const int* __restrict__ mapping, int l) {
    int tid = threadIdx.x;
    int node = blockIdx.x * 8 + (tid >> 5);
    int lane = tid & 31;
    const int* mp = mapping + ((size_t)l * NN + node) * 2;
    int m0 = __ldg(&mp[0]), m1 = __ldg(&mp[1]);
    int d4 = lane * 4;
    float4 hs = make_float4(0.f, 0.f, 0.f, 0.f);
    float4 cs = make_float4(0.f, 0.f, 0.f, 0.f);
    if (m0 > 0) {
        float4 a = *(const float4*)(g_h + (size_t)(m0 - 1) * HP + d4);
        float4 b = *(const float4*)(g_c + (size_t)(m0 - 1) * HD + d4);
        hs.x += a.x; hs.y += a.y; hs.z += a.z; hs.w += a.w;
        cs.x += b.x; cs.y += b.y; cs.z += b.z; cs.w += b.w;
    }
    if (m1 > 0) {
        float4 a = *(const float4*)(g_h + (size_t)(m1 - 1) * HP + d4);
        float4 b = *(const float4*)(g_c + (size_t)(m1 - 1) * HD + d4);
        hs.x += a.x; hs.y += a.y; hs.z += a.z; hs.w += a.w;
        cs.x += b.x; cs.y += b.y; cs.z += b.z; cs.w += b.w;
    }
    hs.x *= 0.5f; hs.y *= 0.5f; hs.z *= 0.5f; hs.w *= 0.5f;
    cs.x *= 0.5f; cs.y *= 0.5f; cs.z *= 0.5f; cs.w *= 0.5f;
    *(float4*)(g_gh + (size_t)node * HP + d4) = hs;
    *(float4*)(g_gc + (size_t)node * HD + d4) = cs;
}

// ---------------- fused gates GEMM + LSTM cell (bf16, 2-stage pipeline) ----------------
// M=16384 (BM=128), cols=512 (BN=128), K=272 (BK=16), 8 warps (4m x 2n).
__global__ __launch_bounds__(256) void step_kernel(int l) {
    __shared__ __align__(16) float As[2][16][SSTR];
    __shared__ __align__(16) float Bs[2][16][SSTR];
    int tid = threadIdx.x;
    int wid = tid >> 5, lane = tid & 31;
    int gid = lane >> 2, tig = lane & 3;
    int m0 = blockIdx.x * 128;
    int cb0 = blockIdx.y * 128;
    int wm = (wid & 3) * 32;
    int wn = (wid >> 2) * 64;

    float acc[2][8][4];
    #pragma unroll
    for (int mi = 0; mi < 2; mi++)
        #pragma unroll
        for (int ni = 0; ni < 8; ni++)
            #pragma unroll
            for (int r = 0; r < 4; r++) acc[mi][ni][r] = 0.0f;

    size_t xoff = (size_t)l * NN;
    int arow = tid >> 5;          // 0..7  (x/B row within half)
    int acol = (lane) * 4;        // 0..124
    int gm  = tid & 127;          // gh path: m within tile
    int gsel = tid >> 7;          // gh path: 0/1

    // LDG one chunk into registers. Half h (0/1) is x-path iff k_base<=128.
    auto ldg = [&](int ci, float4 v[4]) {
        int k0 = ci * 16;
        if (k0 <= 128)
            v[0] = *(const float4*)(g_x + (size_t)(k0 + arow) * LN + xoff + m0 + acol);
        else
            v[0] = *(const float4*)(g_gh + (size_t)(m0 + gm) * HP + (k0 - 136) + gsel * 4);
        if (k0 + 8 <= 128)
            v[1] = *(const float4*)(g_x + (size_t)(k0 + 8 + arow) * LN + xoff + m0 + acol);
        else
            v[1] = *(const float4*)(g_gh + (size_t)(m0 + gm) * HP + (k0 - 128) + gsel * 4);
        v[2] = *(const float4*)(g_W + (size_t)(k0 + arow) * GATES + cb0 + acol);
        v[3] = *(const float4*)(g_W + (size_t)(k0 + 8 + arow) * GATES + cb0 + acol);
    };
    auto sts = [&](int ci, int buf, float4 v[4]) {
        int k0 = ci * 16;
        if (k0 <= 128) {
            *(float4*)&As[buf][arow][acol] = v[0];
        } else {
            int r = gsel * 4;
            As[buf][r    ][gm] = v[0].x; As[buf][r + 1][gm] = v[0].y;
            As[buf][r + 2][gm] = v[0].z; As[buf][r + 3][gm] = v[0].w;
        }
        if (k0 + 8 <= 128) {
            *(float4*)&As[buf][8 + arow][acol] = v[1];
        } else {
            int r = 8 + gsel * 4;
            As[buf][r    ][gm] = v[1].x; As[buf][r + 1][gm] = v[1].y;
            As[buf][r + 2][gm] = v[1].z; As[buf][r + 3][gm] = v[1].w;
        }
        *(float4*)&Bs[buf][arow][acol]     = v[2];
        *(float4*)&Bs[buf][8 + arow][acol] = v[3];
    };

    float4 v[4];
    ldg(0, v);
    sts(0, 0, v);
    __syncthreads();

    #pragma unroll
    for (int ci = 0; ci < 17; ci++) {
        int buf = ci & 1;
        float4 nv[4];
        if (ci < 16) ldg(ci + 1, nv);

        unsigned a[2][4];
        #pragma unroll
        for (int mi = 0; mi < 2; mi++) {
            int mr = wm + mi * 16 + gid;
            a[mi][0] = pk(As[buf][2*tig    ][mr    ], As[buf][2*tig + 1][mr    ]);
            a[mi][1] = pk(As[buf][2*tig    ][mr + 8], As[buf][2*tig + 1][mr + 8]);
            a[mi][2] = pk(As[buf][2*tig + 8][mr    ], As[buf][2*tig + 9][mr    ]);
            a[mi][3] = pk(As[buf][2*tig + 8][mr + 8], As[buf][2*tig + 9][mr + 8]);
        }
        #pragma unroll
        for (int ni = 0; ni < 8; ni++) {
            int nc = wn + ni * 8 + gid;
            unsigned b0 = pk(Bs[buf][2*tig    ][nc], Bs[buf][2*tig + 1][nc]);
            unsigned b1 = pk(Bs[buf][2*tig + 8][nc], Bs[buf][2*tig + 9][nc]);
            #pragma unroll
            for (int mi = 0; mi < 2; mi++) {
                asm volatile(
                    "mma.sync.aligned.m16n8k16.row.col.f32.bf16.bf16.f32 "
                    "{%0,%1,%2,%3}, {%4,%5,%6,%7}, {%8,%9}, {%0,%1,%2,%3};"
                    : "+f"(acc[mi][ni][0]), "+f"(acc[mi][ni][1]),
                      "+f"(acc[mi][ni][2]), "+f"(acc[mi][ni][3])
                    : "r"(a[mi][0]), "r"(a[mi][1]), "r"(a[mi][2]), "r"(a[mi][3]),
                      "r"(b0), "r"(b1));
            }
        }
        if (ci < 16) {
            sts(ci + 1, buf ^ 1, nv);
            __syncthreads();
        }
    }

    // ---- fused cell epilogue (node-major h/c) ----
    #pragma unroll
    for (int mi = 0; mi < 2; mi++) {
        int r0 = m0 + wm + mi * 16 + gid;
        #pragma unroll
        for (int ni = 0; ni < 8; ni++) {
            int c = cb0 + wn + ni * 8 + 2 * tig;
            float cbv0 = __ldg(&g_cbias[c]);
            float cbv1 = __ldg(&g_cbias[c + 1]);
            float v0 = acc[mi][ni][0] + cbv0;
            float v1 = acc[mi][ni][1] + cbv1;
            float v2 = acc[mi][ni][2] + cbv0;
            float v3 = acc[mi][ni][3] + cbv1;
            float p0 = __shfl_xor_sync(0xffffffffu, v0, 1);
            float p1 = __shfl_xor_sync(0xffffffffu, v1, 1);
            float p2 = __shfl_xor_sync(0xffffffffu, v2, 1);
            float p3 = __shfl_xor_sync(0xffffffffu, v3, 1);
            int d = c >> 2;
            int row; float iv, fv, gv, ov;
            if ((tig & 1) == 0) { row = r0;     iv = v0; fv = v1; gv = p0; ov = p1; }
            else                { row = r0 + 8; iv = p2; fv = p3; gv = v2; ov = v3; }
            float gc = g_gc[(size_t)row * HD + d];
            float cn = sigf(fv) * gc + sigf(iv) * tanhf(gv);
            g_c[(size_t)row * HD + d] = cn;
            g_h[(size_t)row * HP + d] = sigf(ov) * tanhf(cn);
        }
    }
}

// ---------------- head MLP ----------------
__global__ void head_kernel(const float* __restrict__ W1, const float* __restrict__ b1,
                            const float* __restrict__ W2, const float* __restrict__ b2,
                            float* __restrict__ out, int rows)
{
    __shared__ float sW1[20 * 128];
    __shared__ float sb1[20], sW2[20];
    __shared__ float sb2;
    int tid = threadIdx.x;
    for (int i = tid; i < 20 * 128; i += 256) sW1[i] = W1[i];
    if (tid < 20) { sb1[tid] = b1[tid]; sW2[tid] = W2[tid]; }
    if (tid == 0) sb2 = b2[0];
    __syncthreads();
    int b = blockIdx.x * 256 + tid;
    if (b >= rows) return;
    float z1[20];
    #pragma unroll
    for (int j = 0; j < 20; j++) z1[j] = sb1[j];
    const float* hrow = g_h + (size_t)b * HP;
    for (int k = 0; k < 128; k++) {
        float hv = hrow[k];
        #pragma unroll
        for (int j = 0; j < 20; j++) z1[j] += hv * sW1[j * 128 + k];
    }
    float z = sb2;
    #pragma unroll
    for (int j = 0; j < 20; j++) z += z1[j] * sW2[j];
    out[b] = 1.0f / (1.0f + expf(-z));
}

// ---------------- launch ----------------
extern "C" void kernel_launch(void* const* d_in, const int* in_sizes, int n_in,
                              void* d_out, int out_size)
{
    const float* op    = (const float*)d_in[0];
    const float* attr  = (const float*)d_in[1];
    const float* filt  = (const float*)d_in[2];
    const float* outp  = (const float*)d_in[3];
    const int*   mapping = (const int*)d_in[4];
    int wb = (in_sizes[5] == 1) ? 6 : 5;
    const float* Wf    = (const float*)d_in[wb + 0];
    const float* bf    = (const float*)d_in[wb + 1];
    const float* Wo    = (const float*)d_in[wb + 2];
    const float* bo    = (const float*)d_in[wb + 3];
    const float* g1    = (const float*)d_in[wb + 4];
    const float* beta1 = (const float*)d_in[wb + 5];
    const float* g2    = (const float*)d_in[wb + 6];
    const float* beta2 = (const float*)d_in[wb + 7];
    const float* Wih   = (const float*)d_in[wb + 8];
    const float* Whh   = (const float*)d_in[wb + 9];
    const float* bih   = (const float*)d_in[wb + 10];
    const float* bhh   = (const float*)d_in[wb + 11];
    const float* W1    = (const float*)d_in[wb + 12];
    const float* b1    = (const float*)d_in[wb + 13];
    const float* W2    = (const float*)d_in[wb + 14];
    const float* b2    = (const float*)d_in[wb + 15];
    float* outptr = (float*)d_out;

    size_t ztotal = (size_t)NN * (HP + HD + HP);
    zero_kernel<<<(int)((ztotal + 255) / 256), 256>>>();
    build_x_kernel<<<LN / 256, 256>>>(op, attr, filt, outp, Wf, bf, Wo, bo);
    stats_kernel<<<dim3(64, 12), 256>>>();
    fold_kernel<<<1, 64>>>(g1, beta1, g2, beta2);
    cbias_kernel<<<1, 512>>>(Wih, bih, bhh);
    weight_kernel<<<KPAD, 512>>>(Wih, Whh);

    for (int t = 0; t < L_STEPS; t++) {
        int l = L_STEPS - 1 - t;
        gather_kernel<<<NN / 8, 256>>>(mapping, l);
        step_kernel<<<dim3(NN / 128, GATES / 128), 256>>>(l);
    }

    head_kernel<<<(out_size + 255) / 256, 256>>>(W1, b1, W2, b2, outptr, out_size);
}

// round 16
// speedup vs baseline: 1.0016x; 1.0016x over previous
#include <cuda_runtime.h>
#include <math.h>

#define L_STEPS 24
#define NN 16384
#define LN (24*16384)          // 393216
#define HD 128
#define HP 136                 // padded node-major row pitch (floats)
#define DIN 136
#define KPAD 272               // padded K (17 chunks of 16)
#define GATES 512
#define SSTR 140

// ---------------- device scratch ----------------
__device__ __align__(128) float g_x[(size_t)DIN * LN];      // [k][LN] feature-major
__device__ __align__(128) float g_W[(size_t)KPAD * GATES];  // [k][col], col = d*4+gate
__device__ __align__(128) float g_cbias[GATES];
__device__ __align__(128) float g_stats[128];
__device__ __align__(128) float g_ss[64], g_st[64];
__device__ __align__(128) float g_h[(size_t)NN * HP];       // [n][136], cols 128..135 zero
__device__ __align__(128) float g_c[(size_t)NN * HD];       // [n][128]
__device__ __align__(128) float g_gh[(size_t)NN * HP];      // [n][136], cols 128..135 zero
__device__ __align__(128) float g_gc[(size_t)NN * HD];      // [n][128]

__device__ __forceinline__ float sigf(float x) { return 1.0f / (1.0f + expf(-x)); }
__device__ __forceinline__ unsigned pk(float lo, float hi) {
    unsigned r; asm("cvt.rn.bf16x2.f32 %0, %1, %2;" : "=r"(r) : "f"(hi), "f"(lo)); return r;
}

// ---------------- zero init: h, c, gh (incl pads), stats ----------------
__global__ void zero_kernel() {
    size_t i = (size_t)blockIdx.x * blockDim.x + threadIdx.x;
    size_t hp = (size_t)NN * HP, hd = (size_t)NN * HD;
    if (i < hp)                 g_h[i] = 0.0f;
    else if (i < hp + hd)       g_c[i - hp] = 0.0f;
    else if (i < 2 * hp + hd)   g_gh[i - hp - hd] = 0.0f;
    if (i < 128) g_stats[i] = 0.0f;
}

// ---------------- build lstm_in columns ----------------
__global__ __launch_bounds__(256) void build_x_kernel(
    const float* __restrict__ op, const float* __restrict__ attr,
    const float* __restrict__ filt, const float* __restrict__ outp,
    const float* __restrict__ Wf, const float* __restrict__ bf,
    const float* __restrict__ Wo, const float* __restrict__ bo)
{
    __shared__ __align__(16) float sWfT[74 * 32];
    __shared__ __align__(16) float sWoT[32 * 32];
    __shared__ float sbf[32], sbo[32];
    int tid = threadIdx.x;
    for (int i = tid; i < 74 * 32; i += 256) { int j = i / 74, k = i % 74; sWfT[k * 32 + j] = Wf[i]; }
    for (int i = tid; i < 32 * 32; i += 256) { int j = i / 32, k = i % 32; sWoT[k * 32 + j] = Wo[i]; }
    if (tid < 32) { sbf[tid] = bf[tid]; sbo[tid] = bo[tid]; }
    __syncthreads();

    size_t r = (size_t)blockIdx.x * 256 + tid;

    const float* opr = op + r * 16;
    #pragma unroll
    for (int k = 0; k < 16; k++) g_x[(size_t)k * LN + r] = opr[k];
    const float* atr = attr + r * 56;
    #pragma unroll 8
    for (int k = 0; k < 56; k++) g_x[(size_t)(16 + k) * LN + r] = atr[k];

    float acc[32];
    #pragma unroll
    for (int j = 0; j < 32; j++) acc[j] = sbf[j];
    const float* frow = filt + r * 74;
    for (int k = 0; k < 74; k++) {
        float fv = __ldg(&frow[k]);
        const float4* wrow = (const float4*)&sWfT[k * 32];
        #pragma unroll
        for (int j4 = 0; j4 < 8; j4++) {
            float4 w = wrow[j4];
            acc[j4*4+0] += fv * w.x; acc[j4*4+1] += fv * w.y;
            acc[j4*4+2] += fv * w.z; acc[j4*4+3] += fv * w.w;
        }
    }
    #pragma unroll
    for (int j = 0; j < 32; j++) {
        float v = acc[j]; v = v > 0.0f ? v : 0.01f * v;
        g_x[(size_t)(72 + j) * LN + r] = v;
    }
    #pragma unroll
    for (int j = 0; j < 32; j++) acc[j] = sbo[j];
    const float* orow = outp + r * 32;
    for (int k = 0; k < 32; k++) {
        float ov = __ldg(&orow[k]);
        const float4* wrow = (const float4*)&sWoT[k * 32];
        #pragma unroll
        for (int j4 = 0; j4 < 8; j4++) {
            float4 w = wrow[j4];
            acc[j4*4+0] += ov * w.x; acc[j4*4+1] += ov * w.y;
            acc[j4*4+2] += ov * w.z; acc[j4*4+3] += ov * w.w;
        }
    }
    #pragma unroll
    for (int j = 0; j < 32; j++) {
        float v = acc[j]; v = v > 0.0f ? v : 0.01f * v;
        g_x[(size_t)(104 + j) * LN + r] = v;
    }
}

// ---------------- BN stats over columns 72..135 ----------------
__global__ void stats_kernel() {
    int f = blockIdx.x;
    size_t col = (size_t)(72 + f) * LN;
    float s = 0.0f, q = 0.0f;
    for (size_t i = (size_t)blockIdx.y * blockDim.x + threadIdx.x; i < LN;
         i += (size_t)gridDim.y * blockDim.x) {
        float v = g_x[col + i];
        s += v; q += v * v;
    }
    for (int o = 16; o > 0; o >>= 1) {
        s += __shfl_down_sync(0xffffffffu, s, o);
        q += __shfl_down_sync(0xffffffffu, q, o);
    }
    __shared__ float shs[8], shq[8];
    int lane = threadIdx.x & 31, w = threadIdx.x >> 5;
    if (lane == 0) { shs[w] = s; shq[w] = q; }
    __syncthreads();
    if (threadIdx.x == 0) {
        float ts = 0.0f, tq = 0.0f;
        for (int i = 0; i < 8; i++) { ts += shs[i]; tq += shq[i]; }
        atomicAdd(&g_stats[f], ts);
        atomicAdd(&g_stats[64 + f], tq);
    }
}

// ---------------- BN fold ----------------
__global__ void fold_kernel(
    const float* __restrict__ g1, const float* __restrict__ beta1,
    const float* __restrict__ g2, const float* __restrict__ beta2)
{
    int tid = threadIdx.x;   // 64
    float mean = g_stats[tid] * (1.0f / (float)LN);
    float var  = g_stats[64 + tid] * (1.0f / (float)LN) - mean * mean;
    float gg = tid < 32 ? g1[tid] : g2[tid - 32];
    float bb = tid < 32 ? beta1[tid] : beta2[tid - 32];
    float sc = gg * rsqrtf(var + 1e-5f);
    g_ss[tid] = sc;
    g_st[tid] = bb - mean * sc;
}

// ---------------- combined bias ----------------
__global__ void cbias_kernel(
    const float* __restrict__ Wih,
    const float* __restrict__ bih, const float* __restrict__ bhh)
{
    int col = threadIdx.x;              // 512; col = d*4 + gate
    int gate = col & 3, d = col >> 2;
    int c = gate * 128 + d;
    const float* wr = Wih + (size_t)c * DIN;
    float cb = bih[c] + bhh[c];
    #pragma unroll
    for (int j = 0; j < 32; j++) cb += g_st[j] * wr[72 + j];
    #pragma unroll
    for (int j = 0; j < 32; j++) cb += g_st[32 + j] * wr[104 + j];
    g_cbias[col] = cb;
}

// ---------------- weight matrix build ----------------
__global__ void weight_kernel(const float* __restrict__ Wih, const float* __restrict__ Whh) {
    int k = blockIdx.x;                 // 0..271
    int col = threadIdx.x;              // 512
    int gate = col & 3, d = col >> 2;
    int c = gate * 128 + d;
    float w;
    if (k < 72)        w = Wih[(size_t)c * DIN + k];
    else if (k < 104)  w = Wih[(size_t)c * DIN + k] * g_ss[k - 72];
    else if (k < 136)  w = Wih[(size_t)c * DIN + k] * g_ss[32 + (k - 104)];
    else if (k < 264)  w = Whh[(size_t)c * HD + (k - 136)];
    else               w = 0.0f;
    g_W[(size_t)k * GATES + col] = w;
}

// ---------------- per-step neighbor gather (node-major, coalesced) ----------------
// 8 nodes per 256-thread block; 32 lanes per node read full rows as float4.
__global__ __launch_bounds__(256) void gather_kernel(const int* __restrict__ mapping, int l) {
    int tid = threadIdx.x;
    int node = blockIdx.x * 8 + (tid >> 5);
    int lane = tid & 31;
    const int* mp = mapping + ((size_t)l * NN + node) * 2;
    int m0 = __ldg(&mp[0]), m1 = __ldg(&mp[1]);
    int d4 = lane * 4;
    float4 hs = make_float4(0.f, 0.f, 0.f, 0.f);
    float4 cs = make_float4(0.f, 0.f, 0.f, 0.f);
    if (m0 > 0) {
        float4 a = *(const float4*)(g_h + (size_t)(m0 - 1) * HP + d4);
        float4 b = *(const float4*)(g_c + (size_t)(m0 - 1) * HD + d4);
        hs.x += a.x; hs.y += a.y; hs.z += a.z; hs.w += a.w;
        cs.x += b.x; cs.y += b.y; cs.z += b.z; cs.w += b.w;
    }
    if (m1 > 0) {
        float4 a = *(const float4*)(g_h + (size_t)(m1 - 1) * HP + d4);
        float4 b = *(const float4*)(g_c + (size_t)(m1 - 1) * HD + d4);
        hs.x += a.x; hs.y += a.y; hs.z += a.z; hs.w += a.w;
        cs.x += b.x; cs.y += b.y; cs.z += b.z; cs.w += b.w;
    }
    hs.x *= 0.5f; hs.y *= 0.5f; hs.z *= 0.5f; hs.w *= 0.5f;
    cs.x *= 0.5f; cs.y *= 0.5f; cs.z *= 0.5f; cs.w *= 0.5f;
    *(float4*)(g_gh + (size_t)node * HP + d4) = hs;
    *(float4*)(g_gc + (size_t)node * HD + d4) = cs;
}

// ---------------- fused gates GEMM + LSTM cell (bf16, 2-stage pipeline) ----------------
// M=16384 (BM=128), cols=512 (BN=128), K=272 (BK=16), 8 warps (4m x 2n).
__global__ __launch_bounds__(256) void step_kernel(int l) {
    __shared__ __align__(16) float As[2][16][SSTR];
    __shared__ __align__(16) float Bs[2][16][SSTR];
    int tid = threadIdx.x;
    int wid = tid >> 5, lane = tid & 31;
    int gid = lane >> 2, tig = lane & 3;
    int m0 = blockIdx.x * 128;
    int cb0 = blockIdx.y * 128;
    int wm = (wid & 3) * 32;
    int wn = (wid >> 2) * 64;

    float acc[2][8][4];
    #pragma unroll
    for (int mi = 0; mi < 2; mi++)
        #pragma unroll
        for (int ni = 0; ni < 8; ni++)
            #pragma unroll
            for (int r = 0; r < 4; r++) acc[mi][ni][r] = 0.0f;

    size_t xoff = (size_t)l * NN;
    int arow = tid >> 5;          // 0..7  (x/B row within half)
    int acol = (lane) * 4;        // 0..124
    int gm  = tid & 127;          // gh path: m within tile
    int gsel = tid >> 7;          // gh path: 0/1

    // LDG one chunk into registers. Half h (0/1) is x-path iff k_base<=128.
    auto ldg = [&](int ci, float4 v[4]) {
        int k0 = ci * 16;
        if (k0 <= 128)
            v[0] = *(const float4*)(g_x + (size_t)(k0 + arow) * LN + xoff + m0 + acol);
        else
            v[0] = *(const float4*)(g_gh + (size_t)(m0 + gm) * HP + (k0 - 136) + gsel * 4);
        if (k0 + 8 <= 128)
            v[1] = *(const float4*)(g_x + (size_t)(k0 + 8 + arow) * LN + xoff + m0 + acol);
        else
            v[1] = *(const float4*)(g_gh + (size_t)(m0 + gm) * HP + (k0 - 128) + gsel * 4);
        v[2] = *(const float4*)(g_W + (size_t)(k0 + arow) * GATES + cb0 + acol);
        v[3] = *(const float4*)(g_W + (size_t)(k0 + 8 + arow) * GATES + cb0 + acol);
    };
    auto sts = [&](int ci, int buf, float4 v[4]) {
        int k0 = ci * 16;
        if (k0 <= 128) {
            *(float4*)&As[buf][arow][acol] = v[0];
        } else {
            int r = gsel * 4;
            As[buf][r    ][gm] = v[0].x; As[buf][r + 1][gm] = v[0].y;
            As[buf][r + 2][gm] = v[0].z; As[buf][r + 3][gm] = v[0].w;
        }
        if (k0 + 8 <= 128) {
            *(float4*)&As[buf][8 + arow][acol] = v[1];
        } else {
            int r = 8 + gsel * 4;
            As[buf][r    ][gm] = v[1].x; As[buf][r + 1][gm] = v[1].y;
            As[buf][r + 2][gm] = v[1].z; As[buf][r + 3][gm] = v[1].w;
        }
        *(float4*)&Bs[buf][arow][acol]     = v[2];
        *(float4*)&Bs[buf][8 + arow][acol] = v[3];
    };

    float4 v[4];
    ldg(0, v);
    sts(0, 0, v);
    __syncthreads();

    #pragma unroll
    for (int ci = 0; ci < 17; ci++) {
        int buf = ci & 1;
        float4 nv[4];
        if (ci < 16) ldg(ci + 1, nv);

        unsigned a[2][4];
        #pragma unroll
        for (int mi = 0; mi < 2; mi++) {
            int mr = wm + mi * 16 + gid;
            a[mi][0] = pk(As[buf][2*tig    ][mr    ], As[buf][2*tig + 1][mr    ]);
            a[mi][1] = pk(As[buf][2*tig    ][mr + 8], As[buf][2*tig + 1][mr + 8]);
            a[mi][2] = pk(As[buf][2*tig + 8][mr    ], As[buf][2*tig + 9][mr    ]);
            a[mi][3] = pk(As[buf][2*tig + 8][mr + 8], As[buf][2*tig + 9][mr + 8]);
        }
        #pragma unroll
        for (int ni = 0; ni < 8; ni++) {
            int nc = wn + ni * 8 + gid;
            unsigned b0 = pk(Bs[buf][2*tig    ][nc], Bs[buf][2*tig + 1][nc]);
            unsigned b1 = pk(Bs[buf][2*tig + 8][nc], Bs[buf][2*tig + 9][nc]);
            #pragma unroll
            for (int mi = 0; mi < 2; mi++) {
                asm volatile(
                    "mma.sync.aligned.m16n8k16.row.col.f32.bf16.bf16.f32 "
                    "{%0,%1,%2,%3}, {%4,%5,%6,%7}, {%8,%9}, {%0,%1,%2,%3};"
                    : "+f"(acc[mi][ni][0]), "+f"(acc[mi][ni][1]),
                      "+f"(acc[mi][ni][2]), "+f"(acc[mi][ni][3])
                    : "r"(a[mi][0]), "r"(a[mi][1]), "r"(a[mi][2]), "r"(a[mi][3]),
                      "r"(b0), "r"(b1));
            }
        }
        if (ci < 16) {
            sts(ci + 1, buf ^ 1, nv);
            __syncthreads();
        }
    }

    // ---- fused cell epilogue (node-major h/c) ----
    #pragma unroll
    for (int mi = 0; mi < 2; mi++) {
        int r0 = m0 + wm + mi * 16 + gid;
        #pragma unroll
        for (int ni = 0; ni < 8; ni++) {
            int c = cb0 + wn + ni * 8 + 2 * tig;
            float cbv0 = __ldg(&g_cbias[c]);
            float cbv1 = __ldg(&g_cbias[c + 1]);
            float v0 = acc[mi][ni][0] + cbv0;
            float v1 = acc[mi][ni][1] + cbv1;
            float v2 = acc[mi][ni][2] + cbv0;
            float v3 = acc[mi][ni][3] + cbv1;
            float p0 = __shfl_xor_sync(0xffffffffu, v0, 1);
            float p1 = __shfl_xor_sync(0xffffffffu, v1, 1);
            float p2 = __shfl_xor_sync(0xffffffffu, v2, 1);
            float p3 = __shfl_xor_sync(0xffffffffu, v3, 1);
            int d = c >> 2;
            int row; float iv, fv, gv, ov;
            if ((tig & 1) == 0) { row = r0;     iv = v0; fv = v1; gv = p0; ov = p1; }
            else                { row = r0 + 8; iv = p2; fv = p3; gv = v2; ov = v3; }
            float gc = g_gc[(size_t)row * HD + d];
            float cn = sigf(fv) * gc + sigf(iv) * tanhf(gv);
            g_c[(size_t)row * HD + d] = cn;
            g_h[(size_t)row * HP + d] = sigf(ov) * tanhf(cn);
        }
    }
}

// ---------------- head MLP ----------------
__global__ void head_kernel(const float* __restrict__ W1, const float* __restrict__ b1,
                            const float* __restrict__ W2, const float* __restrict__ b2,
                            float* __restrict__ out, int rows)
{
    __shared__ float sW1[20 * 128];
    __shared__ float sb1[20], sW2[20];
    __shared__ float sb2;
    int tid = threadIdx.x;
    for (int i = tid; i < 20 * 128; i += 256) sW1[i] = W1[i];
    if (tid < 20) { sb1[tid] = b1[tid]; sW2[tid] = W2[tid]; }
    if (tid == 0) sb2 = b2[0];
    __syncthreads();
    int b = blockIdx.x * 256 + tid;
    if (b >= rows) return;
    float z1[20];
    #pragma unroll
    for (int j = 0; j < 20; j++) z1[j] = sb1[j];
    const float* hrow = g_h + (size_t)b * HP;
    for (int k = 0; k < 128; k++) {
        float hv = hrow[k];
        #pragma unroll
        for (int j = 0; j < 20; j++) z1[j] += hv * sW1[j * 128 + k];
    }
    float z = sb2;
    #pragma unroll
    for (int j = 0; j < 20; j++) z += z1[j] * sW2[j];
    out[b] = 1.0f / (1.0f + expf(-z));
}

// ---------------- launch ----------------
extern "C" void kernel_launch(void* const* d_in, const int* in_sizes, int n_in,
                              void* d_out, int out_size)
{
    const float* op    = (const float*)d_in[0];
    const float* attr  = (const float*)d_in[1];
    const float* filt  = (const float*)d_in[2];
    const float* outp  = (const float*)d_in[3];
    const int*   mapping = (const int*)d_in[4];
    int wb = (in_sizes[5] == 1) ? 6 : 5;
    const float* Wf    = (const float*)d_in[wb + 0];
    const float* bf    = (const float*)d_in[wb + 1];
    const float* Wo    = (const float*)d_in[wb + 2];
    const float* bo    = (const float*)d_in[wb + 3];
    const float* g1    = (const float*)d_in[wb + 4];
    const float* beta1 = (const float*)d_in[wb + 5];
    const float* g2    = (const float*)d_in[wb + 6];
    const float* beta2 = (const float*)d_in[wb + 7];
    const float* Wih   = (const float*)d_in[wb + 8];
    const float* Whh   = (const float*)d_in[wb + 9];
    const float* bih   = (const float*)d_in[wb + 10];
    const float* bhh   = (const float*)d_in[wb + 11];
    const float* W1    = (const float*)d_in[wb + 12];
    const float* b1    = (const float*)d_in[wb + 13];
    const float* W2    = (const float*)d_in[wb + 14];
    const float* b2    = (const float*)d_in[wb + 15];
    float* outptr = (float*)d_out;

    size_t ztotal = (size_t)NN * (HP + HD + HP);
    zero_kernel<<<(int)((ztotal + 255) / 256), 256>>>();
    build_x_kernel<<<LN / 256, 256>>>(op, attr, filt, outp, Wf, bf, Wo, bo);
    stats_kernel<<<dim3(64, 12), 256>>>();
    fold_kernel<<<1, 64>>>(g1, beta1, g2, beta2);
    cbias_kernel<<<1, 512>>>(Wih, bih, bhh);
    weight_kernel<<<KPAD, 512>>>(Wih, Whh);

    for (int t = 0; t < L_STEPS; t++) {
        int l = L_STEPS - 1 - t;
        gather_kernel<<<NN / 8, 256>>>(mapping, l);
        step_kernel<<<dim3(NN / 128, GATES / 128), 256>>>(l);
    }

    head_kernel<<<(out_size + 255) / 256, 256>>>(W1, b1, W2, b2, outptr, out_size);
}